// round 11
// baseline (speedup 1.0000x reference)
#include <cuda_runtime.h>
#include <math.h>

typedef unsigned long long ull;

#define NN 2048
#define MM 128
#define INF 256
#define HH 128
#define NP (NN/2)
#define NCHUNK 16
#define GM 4
#define PTILE 64
#define MSPLIT 16
#define MPS (MM/MSPLIT)     // 8 m per split

#define MIN_STDD 0.3023568
#define MAX_STDD 2.1920868

// ---------------- scratch ----------------
__device__ float g_S2[MM][NP][20];
__device__ float g_hdp2[3][NP][HH][2];
__device__ float g_coarse[NCHUNK][MM][9][HH];
__device__ float g_CU[MM][9][HH];
__device__ ull   g_part[MSPLIT][NP][HH];
__device__ unsigned g_cnt[MM/GM];

// ---------------- f32x2 helpers ----------------
__device__ __forceinline__ ull pack2(float lo, float hi){ ull r; asm("mov.b64 %0,{%1,%2};":"=l"(r):"f"(lo),"f"(hi)); return r; }
__device__ __forceinline__ float2 unpk2(ull v){ float2 f; asm("mov.b64 {%0,%1},%2;":"=f"(f.x),"=f"(f.y):"l"(v)); return f; }
__device__ __forceinline__ ull fma2(ull a, ull b, ull c){ ull d; asm("fma.rn.f32x2 %0,%1,%2,%3;":"=l"(d):"l"(a),"l"(b),"l"(c)); return d; }
__device__ __forceinline__ ull mul2(ull a, ull b){ ull d; asm("mul.rn.f32x2 %0,%1,%2;":"=l"(d):"l"(a),"l"(b)); return d; }
__device__ __forceinline__ ull add2(ull a, ull b){ ull d; asm("add.rn.f32x2 %0,%1,%2;":"=l"(d):"l"(a),"l"(b)); return d; }
__device__ __forceinline__ float ex2f(float x){ float e; asm("ex2.approx.f32 %0,%1;":"=f"(e):"f"(x)); return e; }

// ---------------- KA: SH (blocks 0..127) + pre-MLP (blocks 128..383) ----------------
__global__ void __launch_bounds__(256) kA(const float* __restrict__ gc, const float* __restrict__ cc,
                                          const float* __restrict__ h, const float* __restrict__ Wpre,
                                          const float* __restrict__ bpre, const float* __restrict__ Wdown,
                                          const float* __restrict__ gw) {
    if (blockIdx.x < 128) {
        int m = blockIdx.x;
        float cx = cc[3*m], cy = cc[3*m+1], cz = cc[3*m+2];
        const float is3  = 0.5773502691896258f;
        const float is5  = 0.4472135954999579f;
        const float s3i5 = 0.7745966692414834f;
        for (int p = threadIdx.x; p < NP; p += 256) {
            float k[2][9]; float xx2[2];
            #pragma unroll
            for (int hh = 0; hh < 2; hh++) {
                int n = 2*p + hh;
                float dx = gc[3*n]   - cx;
                float dy = gc[3*n+1] - cy;
                float dz = gc[3*n+2] - cz;
                float x2 = dx*dx + dy*dy + dz*dz + 3e-20f;
                float inv = rsqrtf(x2);
                float x = dx*inv, y = dy*inv, z = dz*inv;
                xx2[hh] = x2;
                k[hh][1] = x*is3;  k[hh][2] = y*is3;  k[hh][3] = z*is3;
                k[hh][4] = s3i5*x*z; k[hh][5] = s3i5*x*y;
                k[hh][6] = (y*y - 0.5f*(x*x + z*z))*is5;
                k[hh][7] = s3i5*y*z; k[hh][8] = 0.5f*s3i5*(z*z - x*x);
            }
            float* q = &g_S2[m][p][0];
            *(float4*)(q+0)  = make_float4(k[0][1],k[1][1],k[0][2],k[1][2]);
            *(float4*)(q+4)  = make_float4(k[0][3],k[1][3],k[0][4],k[1][4]);
            *(float4*)(q+8)  = make_float4(k[0][5],k[1][5],k[0][6],k[1][6]);
            *(float4*)(q+12) = make_float4(k[0][7],k[1][7],k[0][8],k[1][8]);
            *(float4*)(q+16) = make_float4(xx2[0],xx2[1],0.f,0.f);
        }
        return;
    }
    __shared__ float hT[INF][10];
    __shared__ float sT[HH][10];
    int b  = blockIdx.x - 128;
    int n0 = b * 8;
    int t  = threadIdx.x;
    int w  = t & 127;
    int h2 = (t >> 7) * 2;

    for (int idx = t; idx < 8*INF; idx += 256) {
        int r = idx & 7, u = idx >> 3;
        hT[u][r] = h[(n0 + r)*INF + u];
    }
    __syncthreads();

    ull acc[2];
    {
        float b0 = bpre[w];
        acc[0] = pack2(b0, b0); acc[1] = pack2(b0, b0);
    }
    #pragma unroll 8
    for (int u = 0; u < INF; u++) {
        float wv = Wpre[u*HH + w];
        ull w2 = pack2(wv, wv);
        acc[0] = fma2(*(const ull*)&hT[u][2*h2], w2, acc[0]);
        acc[1] = fma2(*(const ull*)&hT[u][2*h2+2], w2, acc[1]);
    }
    #pragma unroll
    for (int j = 0; j < 2; j++) {
        float2 a = unpk2(acc[j]);
        a.x = a.x/(1.f+__expf(-a.x)); a.y = a.y/(1.f+__expf(-a.y));
        *(ull*)&sT[w][2*(h2+j)] = pack2(a.x, a.y);
    }
    __syncthreads();

    double sd = MIN_STDD + (MAX_STDD-MIN_STDD)*(double)w/127.0;
    double iv = 1.0/(2.0*sd*sd);
    const double pi15 = 5.568327996831708;
    float cw = (float)((2.0/3.0)*pow(iv,2.5)/pi15);

    ull gwc[2];
    #pragma unroll
    for (int j = 0; j < 2; j++)
        gwc[j] = pack2(gw[n0+2*(h2+j)]*cw, gw[n0+2*(h2+j)+1]*cw);

    int pbase = b * 4 + h2;
    for (int l = 0; l < 3; l++) {
        const float* Wd = Wdown + l*HH*HH;
        ull a2[2] = {0ull, 0ull};
        #pragma unroll 8
        for (int u = 0; u < HH; u++) {
            float wv = Wd[u*HH + w];
            ull w2 = pack2(wv, wv);
            a2[0] = fma2(*(const ull*)&sT[u][2*h2], w2, a2[0]);
            a2[1] = fma2(*(const ull*)&sT[u][2*h2+2], w2, a2[1]);
        }
        #pragma unroll
        for (int j = 0; j < 2; j++)
            *(ull*)&g_hdp2[l][pbase + j][w][0] = mul2(a2[j], gwc[j]);
    }
}

// ---------------- KB: down accumulation (k-split halves) + fused reduce + GEMM tail ----------------
__global__ void __launch_bounds__(256) k_down(const float* __restrict__ Wup) {
    __shared__ float Ssm[GM][PTILE][20];   // 20 KB
    __shared__ float crs[GM][9][HH];       // 18 KB (tail)
    __shared__ int lastflag;
    int t  = threadIdx.x;
    int w  = t & 127;
    int q  = t >> 7;                       // 0: k0-3, 1: k4-8
    int m0 = blockIdx.x * GM;
    int p0 = blockIdx.y * PTILE;

    double sd = MIN_STDD + (MAX_STDD-MIN_STDD)*(double)w/127.0;
    float niv = (float)(-1.4426950408889634/(2.0*sd*sd));
    ull niv2 = pack2(niv, niv);

    for (int i = t; i < GM*PTILE*5; i += 256) {
        int mi = i/(PTILE*5); int rem = i%(PTILE*5); int p = rem/5; int j = rem%5;
        *(float4*)&Ssm[mi][p][4*j] = *(const float4*)&g_S2[m0+mi][p0+p][4*j];
    }
    __syncthreads();

    if (q == 0) {
        ull acc[GM][4];
        #pragma unroll
        for (int mi = 0; mi < GM; mi++)
            #pragma unroll
            for (int k = 0; k < 4; k++) acc[mi][k] = 0ull;

        ull h0 = *(const ull*)&g_hdp2[0][p0][w][0];
        ull h1 = *(const ull*)&g_hdp2[1][p0][w][0];
        #pragma unroll 1
        for (int p = 0; p < PTILE; p++) {
            ull c0 = h0, c1 = h1;
            if (p + 1 < PTILE) {
                h0 = *(const ull*)&g_hdp2[0][p0+p+1][w][0];
                h1 = *(const ull*)&g_hdp2[1][p0+p+1][w][0];
            }
            #pragma unroll
            for (int mi = 0; mi < GM; mi++) {
                const float* sp = &Ssm[mi][p][0];
                ulonglong2 q01 = *(const ulonglong2*)(sp);
                ull k3p = *(const ull*)(sp + 4);
                ull x2p = *(const ull*)(sp + 16);
                ull qq  = mul2(x2p, niv2);
                float2 ef = unpk2(qq);
                ull ep  = pack2(ex2f(ef.x), ex2f(ef.y));
                ull rp  = mul2(ep, x2p);
                ull t0 = mul2(c0, rp), t1 = mul2(c1, rp);
                acc[mi][0] = add2(acc[mi][0], t0);
                acc[mi][1] = fma2(t1, q01.x, acc[mi][1]);
                acc[mi][2] = fma2(t1, q01.y, acc[mi][2]);
                acc[mi][3] = fma2(t1, k3p,   acc[mi][3]);
            }
        }
        #pragma unroll
        for (int mi = 0; mi < GM; mi++)
            #pragma unroll
            for (int k = 0; k < 4; k++) {
                float2 f = unpk2(acc[mi][k]);
                g_coarse[blockIdx.y][m0+mi][k][w] = f.x + f.y;
            }
    } else {
        ull acc[GM][5];
        #pragma unroll
        for (int mi = 0; mi < GM; mi++)
            #pragma unroll
            for (int k = 0; k < 5; k++) acc[mi][k] = 0ull;

        ull h2 = *(const ull*)&g_hdp2[2][p0][w][0];
        #pragma unroll 1
        for (int p = 0; p < PTILE; p++) {
            ull c2 = h2;
            if (p + 1 < PTILE)
                h2 = *(const ull*)&g_hdp2[2][p0+p+1][w][0];
            #pragma unroll
            for (int mi = 0; mi < GM; mi++) {
                const float* sp = &Ssm[mi][p][0];
                ull k4p = *(const ull*)(sp + 6);
                ulonglong2 q45 = *(const ulonglong2*)(sp + 8);
                ulonglong2 q67 = *(const ulonglong2*)(sp + 12);
                ull x2p = *(const ull*)(sp + 16);
                ull qq  = mul2(x2p, niv2);
                float2 ef = unpk2(qq);
                ull ep  = pack2(ex2f(ef.x), ex2f(ef.y));
                ull rp  = mul2(ep, x2p);
                ull t2 = mul2(c2, rp);
                acc[mi][0] = fma2(t2, k4p,   acc[mi][0]);
                acc[mi][1] = fma2(t2, q45.x, acc[mi][1]);
                acc[mi][2] = fma2(t2, q45.y, acc[mi][2]);
                acc[mi][3] = fma2(t2, q67.x, acc[mi][3]);
                acc[mi][4] = fma2(t2, q67.y, acc[mi][4]);
            }
        }
        #pragma unroll
        for (int mi = 0; mi < GM; mi++)
            #pragma unroll
            for (int k = 0; k < 5; k++) {
                float2 f = unpk2(acc[mi][k]);
                g_coarse[blockIdx.y][m0+mi][4+k][w] = f.x + f.y;
            }
    }

    // ---- last-block: chunk reduce into smem, then CU = cr @ Wup ----
    __threadfence();
    if (t == 0) {
        unsigned old = atomicAdd(&g_cnt[blockIdx.x], 1u);
        lastflag = (old == NCHUNK - 1);
    }
    __syncthreads();
    if (!lastflag) return;
    __threadfence();

    #pragma unroll 1
    for (int mi = 0; mi < GM; mi++) {
        for (int idx = t; idx < 9*HH; idx += 256) {
            int k = idx >> 7, u = idx & 127;
            float s = 0.f;
            #pragma unroll
            for (int ch = 0; ch < NCHUNK; ch++)
                s += g_coarse[ch][m0+mi][k][u];
            crs[mi][k][u] = s;
        }
    }
    if (t == 0) g_cnt[blockIdx.x] = 0;
    __syncthreads();

    if (q == 0) {
        // k0 (W0), k1-3 (W1) for 4 m's
        float a[GM][4];
        #pragma unroll
        for (int mi = 0; mi < GM; mi++)
            #pragma unroll
            for (int k = 0; k < 4; k++) a[mi][k] = 0.f;
        #pragma unroll 4
        for (int u = 0; u < HH; u++) {
            float w0v = Wup[u*HH + w];
            float w1v = Wup[HH*HH + u*HH + w];
            #pragma unroll
            for (int mi = 0; mi < GM; mi++) {
                a[mi][0] += crs[mi][0][u] * w0v;
                a[mi][1] += crs[mi][1][u] * w1v;
                a[mi][2] += crs[mi][2][u] * w1v;
                a[mi][3] += crs[mi][3][u] * w1v;
            }
        }
        #pragma unroll
        for (int mi = 0; mi < GM; mi++)
            #pragma unroll
            for (int k = 0; k < 4; k++)
                g_CU[m0+mi][k][w] = a[mi][k];
    } else {
        float a[GM][5];
        #pragma unroll
        for (int mi = 0; mi < GM; mi++)
            #pragma unroll
            for (int k = 0; k < 5; k++) a[mi][k] = 0.f;
        const float* W2 = Wup + 2*HH*HH;
        #pragma unroll 4
        for (int u = 0; u < HH; u++) {
            float w2v = W2[u*HH + w];
            #pragma unroll
            for (int mi = 0; mi < GM; mi++) {
                a[mi][0] += crs[mi][4][u] * w2v;
                a[mi][1] += crs[mi][5][u] * w2v;
                a[mi][2] += crs[mi][6][u] * w2v;
                a[mi][3] += crs[mi][7][u] * w2v;
                a[mi][4] += crs[mi][8][u] * w2v;
            }
        }
        #pragma unroll
        for (int mi = 0; mi < GM; mi++)
            #pragma unroll
            for (int k = 0; k < 5; k++)
                g_CU[m0+mi][4+k][w] = a[mi][k];
    }
}

// ---------------- KD: split-K up contraction -> partials (512 thr, 4 q-groups) ----------------
__global__ void __launch_bounds__(512) k_upA() {
    __shared__ float CUs[2][9*HH];     // 4.6 KB x2
    __shared__ float Ss[2][32*20];     // 2.56 KB x2
    int t = threadIdx.x;
    int w = t & 127, q = t >> 7;       // q in {0..3}: pairs q*8..q*8+7
    int p0 = blockIdx.x * 32;
    int mbase = blockIdx.y * MPS;

    auto fetch = [&](int s, int i) -> float4 {
        int m = mbase + s;
        if (i < 288) return ((const float4*)&g_CU[m][0][0])[i];
        return ((const float4*)&g_S2[m][p0][0])[i - 288];
    };
    auto store = [&](int buf, int i, float4 v) {
        if (i < 288) ((float4*)&CUs[buf][0])[i] = v;
        else         ((float4*)&Ss[buf][0])[i - 288] = v;
    };

    bool doF = (t < 448);
    float4 r0;
    if (doF) r0 = fetch(0, t);
    if (doF) store(0, t, r0);
    __syncthreads();

    ull acc[8];
    #pragma unroll
    for (int j = 0; j < 8; j++) acc[j] = 0ull;

    #pragma unroll 1
    for (int s = 0; s < MPS; s++) {
        int buf = s & 1;
        if (s + 1 < MPS && doF) r0 = fetch(s+1, t);
        ull cu[9];
        #pragma unroll
        for (int k = 0; k < 9; k++) { float c = CUs[buf][k*HH + w]; cu[k] = pack2(c, c); }
        #pragma unroll
        for (int j = 0; j < 8; j++) {
            const float* sp = &Ss[buf][(q*8 + j)*20];
            ulonglong2 q01 = *(const ulonglong2*)(sp);
            ulonglong2 q23 = *(const ulonglong2*)(sp + 4);
            ulonglong2 q45 = *(const ulonglong2*)(sp + 8);
            ulonglong2 q67 = *(const ulonglong2*)(sp + 12);
            ull a = acc[j];
            a = add2(a, cu[0]);
            a = fma2(cu[1], q01.x, a);
            a = fma2(cu[2], q01.y, a);
            a = fma2(cu[3], q23.x, a);
            a = fma2(cu[4], q23.y, a);
            a = fma2(cu[5], q45.x, a);
            a = fma2(cu[6], q45.y, a);
            a = fma2(cu[7], q67.x, a);
            a = fma2(cu[8], q67.y, a);
            acc[j] = a;
        }
        __syncthreads();
        if (s + 1 < MPS) {
            int nb = buf ^ 1;
            if (doF) store(nb, t, r0);
            __syncthreads();
        }
    }

    #pragma unroll
    for (int j = 0; j < 8; j++)
        g_part[blockIdx.y][p0 + q*8 + j][w] = acc[j];
}

// ---------------- KE: sum partials + post-MLP + silu -> out ----------------
__global__ void __launch_bounds__(256) k_fin(const float* __restrict__ Wpost,
                                             const float* __restrict__ bpost,
                                             float* __restrict__ out) {
    __shared__ ull osm[4][HH];
    int t = threadIdx.x;
    int w = t & 127, q = t >> 7;
    int p0 = blockIdx.x * 4;

    #pragma unroll
    for (int j = 0; j < 2; j++) {
        int p = p0 + q*2 + j;
        ull s = 0ull;
        #pragma unroll
        for (int sp = 0; sp < MSPLIT; sp++)
            s = add2(s, g_part[sp][p][w]);
        osm[q*2 + j][w] = s;
    }
    __syncthreads();

    float bp = bpost[w];
    ull fo0 = pack2(bp, bp), fo1 = pack2(bp, bp);
    #pragma unroll 8
    for (int u = 0; u < HH; u++) {
        float wv = Wpost[u*HH + w];
        ull wv2 = pack2(wv, wv);
        fo0 = fma2(osm[q*2 + 0][u], wv2, fo0);
        fo1 = fma2(osm[q*2 + 1][u], wv2, fo1);
    }
    float2 f0 = unpk2(fo0), f1 = unpk2(fo1);
    int r0i = 2*(p0 + 2*q);
    out[(long)(r0i+0)*HH + w] = f0.x/(1.f+__expf(-f0.x));
    out[(long)(r0i+1)*HH + w] = f0.y/(1.f+__expf(-f0.y));
    out[(long)(r0i+2)*HH + w] = f1.x/(1.f+__expf(-f1.x));
    out[(long)(r0i+3)*HH + w] = f1.y/(1.f+__expf(-f1.y));
}

// ---------------- launch ----------------
extern "C" void kernel_launch(void* const* d_in, const int* in_sizes, int n_in,
                              void* d_out, int out_size) {
    const float* h     = (const float*)d_in[0];
    const float* gc    = (const float*)d_in[1];
    const float* cc    = (const float*)d_in[2];
    const float* gw    = (const float*)d_in[3];
    const float* Wpre  = (const float*)d_in[4];
    const float* bpre  = (const float*)d_in[5];
    const float* Wdown = (const float*)d_in[6];
    const float* Wup   = (const float*)d_in[7];
    const float* Wpost = (const float*)d_in[8];
    const float* bpost = (const float*)d_in[9];
    float* out = (float*)d_out;

    kA    <<<384, 256>>>(gc, cc, h, Wpre, bpre, Wdown, gw);
    k_down<<<dim3(MM/GM, NCHUNK), 256>>>(Wup);
    k_upA <<<dim3(NP/32, MSPLIT), 512>>>();
    k_fin <<<NP/4, 256>>>(Wpost, bpost, out);
}

// round 12
// speedup vs baseline: 1.1636x; 1.1636x over previous
#include <cuda_runtime.h>
#include <math.h>

typedef unsigned long long ull;

#define NN 2048
#define MM 128
#define INF 256
#define HH 128
#define NP (NN/2)
#define NCHUNK 16
#define GM 4
#define PTILE 64
#define MSPLIT 8
#define MPS (MM/MSPLIT)     // 16 m per split

#define MIN_STDD 0.3023568
#define MAX_STDD 2.1920868

// ---------------- scratch ----------------
__device__ float g_S2[MM][NP][20];
__device__ float g_hdp2[3][NP][HH][2];
__device__ float g_coarse[NCHUNK][MM][9][HH];
__device__ float g_cr[MM][9][HH];
__device__ float g_CU[MM][9][HH];
__device__ ull   g_part[MSPLIT][NP][HH];
__device__ unsigned g_cnt[MM/GM];

// ---------------- f32x2 helpers ----------------
__device__ __forceinline__ ull pack2(float lo, float hi){ ull r; asm("mov.b64 %0,{%1,%2};":"=l"(r):"f"(lo),"f"(hi)); return r; }
__device__ __forceinline__ float2 unpk2(ull v){ float2 f; asm("mov.b64 {%0,%1},%2;":"=f"(f.x),"=f"(f.y):"l"(v)); return f; }
__device__ __forceinline__ ull fma2(ull a, ull b, ull c){ ull d; asm("fma.rn.f32x2 %0,%1,%2,%3;":"=l"(d):"l"(a),"l"(b),"l"(c)); return d; }
__device__ __forceinline__ ull mul2(ull a, ull b){ ull d; asm("mul.rn.f32x2 %0,%1,%2;":"=l"(d):"l"(a),"l"(b)); return d; }
__device__ __forceinline__ ull add2(ull a, ull b){ ull d; asm("add.rn.f32x2 %0,%1,%2;":"=l"(d):"l"(a),"l"(b)); return d; }
__device__ __forceinline__ float ex2f(float x){ float e; asm("ex2.approx.f32 %0,%1;":"=f"(e):"f"(x)); return e; }

// ---------------- KA: SH (blocks 0..127) + pre-MLP (blocks 128..383) ----------------
__global__ void __launch_bounds__(256) kA(const float* __restrict__ gc, const float* __restrict__ cc,
                                          const float* __restrict__ h, const float* __restrict__ Wpre,
                                          const float* __restrict__ bpre, const float* __restrict__ Wdown,
                                          const float* __restrict__ gw) {
    if (blockIdx.x < 128) {
        int m = blockIdx.x;
        float cx = cc[3*m], cy = cc[3*m+1], cz = cc[3*m+2];
        const float is3  = 0.5773502691896258f;
        const float is5  = 0.4472135954999579f;
        const float s3i5 = 0.7745966692414834f;
        for (int p = threadIdx.x; p < NP; p += 256) {
            float k[2][9]; float xx2[2];
            #pragma unroll
            for (int hh = 0; hh < 2; hh++) {
                int n = 2*p + hh;
                float dx = gc[3*n]   - cx;
                float dy = gc[3*n+1] - cy;
                float dz = gc[3*n+2] - cz;
                float x2 = dx*dx + dy*dy + dz*dz + 3e-20f;
                float inv = rsqrtf(x2);
                float x = dx*inv, y = dy*inv, z = dz*inv;
                xx2[hh] = x2;
                k[hh][1] = x*is3;  k[hh][2] = y*is3;  k[hh][3] = z*is3;
                k[hh][4] = s3i5*x*z; k[hh][5] = s3i5*x*y;
                k[hh][6] = (y*y - 0.5f*(x*x + z*z))*is5;
                k[hh][7] = s3i5*y*z; k[hh][8] = 0.5f*s3i5*(z*z - x*x);
            }
            float* q = &g_S2[m][p][0];
            *(float4*)(q+0)  = make_float4(k[0][1],k[1][1],k[0][2],k[1][2]);
            *(float4*)(q+4)  = make_float4(k[0][3],k[1][3],k[0][4],k[1][4]);
            *(float4*)(q+8)  = make_float4(k[0][5],k[1][5],k[0][6],k[1][6]);
            *(float4*)(q+12) = make_float4(k[0][7],k[1][7],k[0][8],k[1][8]);
            *(float4*)(q+16) = make_float4(xx2[0],xx2[1],0.f,0.f);
        }
        return;
    }
    __shared__ float hT[INF][10];
    __shared__ float sT[HH][10];
    int b  = blockIdx.x - 128;
    int n0 = b * 8;
    int t  = threadIdx.x;
    int w  = t & 127;
    int h2 = (t >> 7) * 2;

    for (int idx = t; idx < 8*INF; idx += 256) {
        int r = idx & 7, u = idx >> 3;
        hT[u][r] = h[(n0 + r)*INF + u];
    }
    __syncthreads();

    ull acc[2];
    {
        float b0 = bpre[w];
        acc[0] = pack2(b0, b0); acc[1] = pack2(b0, b0);
    }
    #pragma unroll 8
    for (int u = 0; u < INF; u++) {
        float wv = Wpre[u*HH + w];
        ull w2 = pack2(wv, wv);
        acc[0] = fma2(*(const ull*)&hT[u][2*h2], w2, acc[0]);
        acc[1] = fma2(*(const ull*)&hT[u][2*h2+2], w2, acc[1]);
    }
    #pragma unroll
    for (int j = 0; j < 2; j++) {
        float2 a = unpk2(acc[j]);
        a.x = a.x/(1.f+__expf(-a.x)); a.y = a.y/(1.f+__expf(-a.y));
        *(ull*)&sT[w][2*(h2+j)] = pack2(a.x, a.y);
    }
    __syncthreads();

    double sd = MIN_STDD + (MAX_STDD-MIN_STDD)*(double)w/127.0;
    double iv = 1.0/(2.0*sd*sd);
    const double pi15 = 5.568327996831708;
    float cw = (float)((2.0/3.0)*pow(iv,2.5)/pi15);

    ull gwc[2];
    #pragma unroll
    for (int j = 0; j < 2; j++)
        gwc[j] = pack2(gw[n0+2*(h2+j)]*cw, gw[n0+2*(h2+j)+1]*cw);

    int pbase = b * 4 + h2;
    for (int l = 0; l < 3; l++) {
        const float* Wd = Wdown + l*HH*HH;
        ull a2[2] = {0ull, 0ull};
        #pragma unroll 8
        for (int u = 0; u < HH; u++) {
            float wv = Wd[u*HH + w];
            ull w2 = pack2(wv, wv);
            a2[0] = fma2(*(const ull*)&sT[u][2*h2], w2, a2[0]);
            a2[1] = fma2(*(const ull*)&sT[u][2*h2+2], w2, a2[1]);
        }
        #pragma unroll
        for (int j = 0; j < 2; j++)
            *(ull*)&g_hdp2[l][pbase + j][w][0] = mul2(a2[j], gwc[j]);
    }
}

// ---------------- KB: down accumulation + fused last-block chunk reduce (R10) ----------------
__global__ void __launch_bounds__(128) k_down() {
    __shared__ float Ssm[GM][PTILE][20];
    int t  = threadIdx.x;
    int m0 = blockIdx.x * GM;
    int p0 = blockIdx.y * PTILE;

    double sd = MIN_STDD + (MAX_STDD-MIN_STDD)*(double)t/127.0;
    float niv = (float)(-1.4426950408889634/(2.0*sd*sd));
    ull niv2 = pack2(niv, niv);

    for (int i = t; i < GM*PTILE*5; i += 128) {
        int mi = i/(PTILE*5); int rem = i%(PTILE*5); int p = rem/5; int j = rem%5;
        *(float4*)&Ssm[mi][p][4*j] = *(const float4*)&g_S2[m0+mi][p0+p][4*j];
    }
    ull acc[GM][9];
    #pragma unroll
    for (int mi = 0; mi < GM; mi++)
        #pragma unroll
        for (int k = 0; k < 9; k++) acc[mi][k] = 0ull;
    __syncthreads();

    ull h0 = *(const ull*)&g_hdp2[0][p0][t][0];
    ull h1 = *(const ull*)&g_hdp2[1][p0][t][0];
    ull h2 = *(const ull*)&g_hdp2[2][p0][t][0];

    #pragma unroll 1
    for (int p = 0; p < PTILE; p++) {
        ull c0 = h0, c1 = h1, c2 = h2;
        if (p + 1 < PTILE) {
            h0 = *(const ull*)&g_hdp2[0][p0+p+1][t][0];
            h1 = *(const ull*)&g_hdp2[1][p0+p+1][t][0];
            h2 = *(const ull*)&g_hdp2[2][p0+p+1][t][0];
        }
        #pragma unroll
        for (int mi = 0; mi < GM; mi++) {
            const float* sp = &Ssm[mi][p][0];
            ulonglong2 q01 = *(const ulonglong2*)(sp);
            ulonglong2 q23 = *(const ulonglong2*)(sp + 4);
            ulonglong2 q45 = *(const ulonglong2*)(sp + 8);
            ulonglong2 q67 = *(const ulonglong2*)(sp + 12);
            ull x2p = *(const ull*)(sp + 16);
            ull qq  = mul2(x2p, niv2);
            float2 ef = unpk2(qq);
            ull ep  = pack2(ex2f(ef.x), ex2f(ef.y));
            ull rp  = mul2(ep, x2p);
            ull t0 = mul2(c0, rp), t1 = mul2(c1, rp), t2 = mul2(c2, rp);
            acc[mi][0] = add2(acc[mi][0], t0);
            acc[mi][1] = fma2(t1, q01.x, acc[mi][1]);
            acc[mi][2] = fma2(t1, q01.y, acc[mi][2]);
            acc[mi][3] = fma2(t1, q23.x, acc[mi][3]);
            acc[mi][4] = fma2(t2, q23.y, acc[mi][4]);
            acc[mi][5] = fma2(t2, q45.x, acc[mi][5]);
            acc[mi][6] = fma2(t2, q45.y, acc[mi][6]);
            acc[mi][7] = fma2(t2, q67.x, acc[mi][7]);
            acc[mi][8] = fma2(t2, q67.y, acc[mi][8]);
        }
    }
    #pragma unroll
    for (int mi = 0; mi < GM; mi++)
        #pragma unroll
        for (int k = 0; k < 9; k++) {
            float2 f = unpk2(acc[mi][k]);
            g_coarse[blockIdx.y][m0+mi][k][t] = f.x + f.y;
        }

    __threadfence();
    __shared__ int lastflag;
    if (t == 0) {
        unsigned old = atomicAdd(&g_cnt[blockIdx.x], 1u);
        lastflag = (old == NCHUNK - 1);
    }
    __syncthreads();
    if (!lastflag) return;
    __threadfence();

    #pragma unroll 1
    for (int mi = 0; mi < GM; mi++) {
        #pragma unroll
        for (int k = 0; k < 9; k++) {
            float s = 0.f;
            #pragma unroll
            for (int ch = 0; ch < NCHUNK; ch++)
                s += g_coarse[ch][m0+mi][k][t];
            g_cr[m0+mi][k][t] = s;
        }
    }
    if (t == 0) g_cnt[blockIdx.x] = 0;
}

// ---------------- KC: CU = coarse @ Wup, one block per (m, l) (R10) ----------------
__global__ void __launch_bounds__(128) k_gemm(const float* __restrict__ Wup) {
    __shared__ float csm[5][HH];
    int m = blockIdx.x;
    int l = blockIdx.y;
    int t = threadIdx.x;
    const float* Wl = Wup + l*HH*HH;

    if (l == 0) {
        csm[0][t] = g_cr[m][0][t];
        __syncthreads();
        float a = 0.f;
        #pragma unroll 8
        for (int u = 0; u < HH; u++) a += csm[0][u] * Wl[u*HH + t];
        g_CU[m][0][t] = a;
    } else if (l == 1) {
        #pragma unroll
        for (int k = 0; k < 3; k++) csm[k][t] = g_cr[m][1+k][t];
        __syncthreads();
        float a0 = 0.f, a1 = 0.f, a2 = 0.f;
        #pragma unroll 8
        for (int u = 0; u < HH; u++) {
            float wv = Wl[u*HH + t];
            a0 += csm[0][u]*wv; a1 += csm[1][u]*wv; a2 += csm[2][u]*wv;
        }
        g_CU[m][1][t] = a0; g_CU[m][2][t] = a1; g_CU[m][3][t] = a2;
    } else {
        #pragma unroll
        for (int k = 0; k < 5; k++) csm[k][t] = g_cr[m][4+k][t];
        __syncthreads();
        float a0=0.f,a1=0.f,a2=0.f,a3=0.f,a4=0.f;
        #pragma unroll 8
        for (int u = 0; u < HH; u++) {
            float wv = Wl[u*HH + t];
            a0 += csm[0][u]*wv; a1 += csm[1][u]*wv; a2 += csm[2][u]*wv;
            a3 += csm[3][u]*wv; a4 += csm[4][u]*wv;
        }
        g_CU[m][4][t]=a0; g_CU[m][5][t]=a1; g_CU[m][6][t]=a2;
        g_CU[m][7][t]=a3; g_CU[m][8][t]=a4;
    }
}

// ---------------- KD: split-K up contraction -> partials ----------------
// grid (64 n-tiles, 8 m-splits), 256 threads. Tile: 16 pairs x 16 m-stages.
__global__ void __launch_bounds__(256) k_upA() {
    __shared__ float CUs[2][9*HH];     // 4.6 KB x2
    __shared__ float Ss[2][16*20];     // 1.28 KB x2
    int t = threadIdx.x;
    int w = t & 127, q = t >> 7;       // q in {0,1}: pairs q*8..q*8+7
    int p0 = blockIdx.x * 16;
    int mbase = blockIdx.y * MPS;

    // stage fetch: 288 CU float4 + 80 S float4 = 368
    auto fetch = [&](int s, int i) -> float4 {
        int m = mbase + s;
        if (i < 288) return ((const float4*)&g_CU[m][0][0])[i];
        return ((const float4*)&g_S2[m][p0][0])[i - 288];
    };
    auto store = [&](int buf, int i, float4 v) {
        if (i < 288) ((float4*)&CUs[buf][0])[i] = v;
        else         ((float4*)&Ss[buf][0])[i - 288] = v;
    };

    int i0 = t, i1 = t + 256;          // i1 valid when < 368 (t < 112)
    bool h1v = (i1 < 368);

    float4 r0 = fetch(0, i0), r1;
    if (h1v) r1 = fetch(0, i1);
    store(0, i0, r0); if (h1v) store(0, i1, r1);
    __syncthreads();

    ull acc[8];
    #pragma unroll
    for (int j = 0; j < 8; j++) acc[j] = 0ull;

    #pragma unroll 1
    for (int s = 0; s < MPS; s++) {
        int buf = s & 1;
        if (s + 1 < MPS) {
            r0 = fetch(s+1, i0);
            if (h1v) r1 = fetch(s+1, i1);
        }
        ull cu[9];
        #pragma unroll
        for (int k = 0; k < 9; k++) { float c = CUs[buf][k*HH + w]; cu[k] = pack2(c, c); }
        #pragma unroll
        for (int j = 0; j < 8; j++) {
            const float* sp = &Ss[buf][(q*8 + j)*20];
            ulonglong2 q01 = *(const ulonglong2*)(sp);
            ulonglong2 q23 = *(const ulonglong2*)(sp + 4);
            ulonglong2 q45 = *(const ulonglong2*)(sp + 8);
            ulonglong2 q67 = *(const ulonglong2*)(sp + 12);
            ull a = acc[j];
            a = add2(a, cu[0]);
            a = fma2(cu[1], q01.x, a);
            a = fma2(cu[2], q01.y, a);
            a = fma2(cu[3], q23.x, a);
            a = fma2(cu[4], q23.y, a);
            a = fma2(cu[5], q45.x, a);
            a = fma2(cu[6], q45.y, a);
            a = fma2(cu[7], q67.x, a);
            a = fma2(cu[8], q67.y, a);
            acc[j] = a;
        }
        __syncthreads();
        if (s + 1 < MPS) {
            int nb = buf ^ 1;
            store(nb, i0, r0); if (h1v) store(nb, i1, r1);
            __syncthreads();
        }
    }

    #pragma unroll
    for (int j = 0; j < 8; j++)
        g_part[blockIdx.y][p0 + q*8 + j][w] = acc[j];
}

// ---------------- KE: sum partials + post-MLP + silu -> out ----------------
__global__ void __launch_bounds__(256) k_fin(const float* __restrict__ Wpost,
                                             const float* __restrict__ bpost,
                                             float* __restrict__ out) {
    __shared__ ull osm[4][HH];
    int t = threadIdx.x;
    int w = t & 127, q = t >> 7;
    int p0 = blockIdx.x * 4;

    #pragma unroll
    for (int j = 0; j < 2; j++) {
        int p = p0 + q*2 + j;
        ull s = 0ull;
        #pragma unroll
        for (int sp = 0; sp < MSPLIT; sp++)
            s = add2(s, g_part[sp][p][w]);
        osm[q*2 + j][w] = s;
    }
    __syncthreads();

    float bp = bpost[w];
    ull fo0 = pack2(bp, bp), fo1 = pack2(bp, bp);
    #pragma unroll 8
    for (int u = 0; u < HH; u++) {
        float wv = Wpost[u*HH + w];
        ull wv2 = pack2(wv, wv);
        fo0 = fma2(osm[q*2 + 0][u], wv2, fo0);
        fo1 = fma2(osm[q*2 + 1][u], wv2, fo1);
    }
    float2 f0 = unpk2(fo0), f1 = unpk2(fo1);
    int r0i = 2*(p0 + 2*q);
    out[(long)(r0i+0)*HH + w] = f0.x/(1.f+__expf(-f0.x));
    out[(long)(r0i+1)*HH + w] = f0.y/(1.f+__expf(-f0.y));
    out[(long)(r0i+2)*HH + w] = f1.x/(1.f+__expf(-f1.x));
    out[(long)(r0i+3)*HH + w] = f1.y/(1.f+__expf(-f1.y));
}

// ---------------- launch ----------------
extern "C" void kernel_launch(void* const* d_in, const int* in_sizes, int n_in,
                              void* d_out, int out_size) {
    const float* h     = (const float*)d_in[0];
    const float* gc    = (const float*)d_in[1];
    const float* cc    = (const float*)d_in[2];
    const float* gw    = (const float*)d_in[3];
    const float* Wpre  = (const float*)d_in[4];
    const float* bpre  = (const float*)d_in[5];
    const float* Wdown = (const float*)d_in[6];
    const float* Wup   = (const float*)d_in[7];
    const float* Wpost = (const float*)d_in[8];
    const float* bpost = (const float*)d_in[9];
    float* out = (float*)d_out;

    kA    <<<384, 256>>>(gc, cc, h, Wpre, bpre, Wdown, gw);
    k_down<<<dim3(MM/GM, NCHUNK), 128>>>();
    k_gemm<<<dim3(MM, 3), 128>>>(Wup);
    k_upA <<<dim3(NP/16, MSPLIT), 256>>>();
    k_fin <<<NP/4, 256>>>(Wpost, bpost, out);
}

// round 13
// speedup vs baseline: 1.1666x; 1.0026x over previous
#include <cuda_runtime.h>
#include <math.h>

typedef unsigned long long ull;

#define NN 2048
#define MM 128
#define INF 256
#define HH 128
#define NP (NN/2)
#define NCHUNK 16
#define GM 4
#define PTILE 64
#define MSPLIT 8
#define MPS (MM/MSPLIT)     // 16 m per split

#define MIN_STDD 0.3023568
#define MAX_STDD 2.1920868

// ---------------- scratch ----------------
__device__ float g_S2[MM][NP][20];
__device__ float g_hdp2[3][NP][HH][2];
__device__ float g_coarse[NCHUNK][MM][9][HH];
__device__ float g_cr[MM][9][HH];
__device__ float g_CU[MM][9][HH];
__device__ ull   g_part[MSPLIT][NP][HH];
__device__ unsigned g_cnt[MM/GM];

// ---------------- f32x2 helpers ----------------
__device__ __forceinline__ ull pack2(float lo, float hi){ ull r; asm("mov.b64 %0,{%1,%2};":"=l"(r):"f"(lo),"f"(hi)); return r; }
__device__ __forceinline__ float2 unpk2(ull v){ float2 f; asm("mov.b64 {%0,%1},%2;":"=f"(f.x),"=f"(f.y):"l"(v)); return f; }
__device__ __forceinline__ ull fma2(ull a, ull b, ull c){ ull d; asm("fma.rn.f32x2 %0,%1,%2,%3;":"=l"(d):"l"(a),"l"(b),"l"(c)); return d; }
__device__ __forceinline__ ull mul2(ull a, ull b){ ull d; asm("mul.rn.f32x2 %0,%1,%2;":"=l"(d):"l"(a),"l"(b)); return d; }
__device__ __forceinline__ ull add2(ull a, ull b){ ull d; asm("add.rn.f32x2 %0,%1,%2;":"=l"(d):"l"(a),"l"(b)); return d; }
__device__ __forceinline__ float ex2f(float x){ float e; asm("ex2.approx.f32 %0,%1;":"=f"(e):"f"(x)); return e; }

// ---------------- KA: SH (blocks 0..127) + pre-MLP (blocks 128..383) ----------------
__global__ void __launch_bounds__(256) kA(const float* __restrict__ gc, const float* __restrict__ cc,
                                          const float* __restrict__ h, const float* __restrict__ Wpre,
                                          const float* __restrict__ bpre, const float* __restrict__ Wdown,
                                          const float* __restrict__ gw) {
    if (blockIdx.x < 128) {
        int m = blockIdx.x;
        float cx = cc[3*m], cy = cc[3*m+1], cz = cc[3*m+2];
        const float is3  = 0.5773502691896258f;
        const float is5  = 0.4472135954999579f;
        const float s3i5 = 0.7745966692414834f;
        for (int p = threadIdx.x; p < NP; p += 256) {
            float k[2][9]; float xx2[2];
            #pragma unroll
            for (int hh = 0; hh < 2; hh++) {
                int n = 2*p + hh;
                float dx = gc[3*n]   - cx;
                float dy = gc[3*n+1] - cy;
                float dz = gc[3*n+2] - cz;
                float x2 = dx*dx + dy*dy + dz*dz + 3e-20f;
                float inv = rsqrtf(x2);
                float x = dx*inv, y = dy*inv, z = dz*inv;
                xx2[hh] = x2;
                k[hh][1] = x*is3;  k[hh][2] = y*is3;  k[hh][3] = z*is3;
                k[hh][4] = s3i5*x*z; k[hh][5] = s3i5*x*y;
                k[hh][6] = (y*y - 0.5f*(x*x + z*z))*is5;
                k[hh][7] = s3i5*y*z; k[hh][8] = 0.5f*s3i5*(z*z - x*x);
            }
            float* q = &g_S2[m][p][0];
            *(float4*)(q+0)  = make_float4(k[0][1],k[1][1],k[0][2],k[1][2]);
            *(float4*)(q+4)  = make_float4(k[0][3],k[1][3],k[0][4],k[1][4]);
            *(float4*)(q+8)  = make_float4(k[0][5],k[1][5],k[0][6],k[1][6]);
            *(float4*)(q+12) = make_float4(k[0][7],k[1][7],k[0][8],k[1][8]);
            *(float4*)(q+16) = make_float4(xx2[0],xx2[1],0.f,0.f);
        }
        return;
    }
    __shared__ float hT[INF][10];
    __shared__ float sT[HH][10];
    int b  = blockIdx.x - 128;
    int n0 = b * 8;
    int t  = threadIdx.x;
    int w  = t & 127;
    int h2 = (t >> 7) * 2;

    for (int idx = t; idx < 8*INF; idx += 256) {
        int r = idx & 7, u = idx >> 3;
        hT[u][r] = h[(n0 + r)*INF + u];
    }
    __syncthreads();

    ull acc[2];
    {
        float b0 = bpre[w];
        acc[0] = pack2(b0, b0); acc[1] = pack2(b0, b0);
    }
    #pragma unroll 8
    for (int u = 0; u < INF; u++) {
        float wv = Wpre[u*HH + w];
        ull w2 = pack2(wv, wv);
        acc[0] = fma2(*(const ull*)&hT[u][2*h2], w2, acc[0]);
        acc[1] = fma2(*(const ull*)&hT[u][2*h2+2], w2, acc[1]);
    }
    #pragma unroll
    for (int j = 0; j < 2; j++) {
        float2 a = unpk2(acc[j]);
        a.x = a.x/(1.f+__expf(-a.x)); a.y = a.y/(1.f+__expf(-a.y));
        *(ull*)&sT[w][2*(h2+j)] = pack2(a.x, a.y);
    }
    __syncthreads();

    double sd = MIN_STDD + (MAX_STDD-MIN_STDD)*(double)w/127.0;
    double iv = 1.0/(2.0*sd*sd);
    const double pi15 = 5.568327996831708;
    float cw = (float)((2.0/3.0)*pow(iv,2.5)/pi15);

    ull gwc[2];
    #pragma unroll
    for (int j = 0; j < 2; j++)
        gwc[j] = pack2(gw[n0+2*(h2+j)]*cw, gw[n0+2*(h2+j)+1]*cw);

    int pbase = b * 4 + h2;
    for (int l = 0; l < 3; l++) {
        const float* Wd = Wdown + l*HH*HH;
        ull a2[2] = {0ull, 0ull};
        #pragma unroll 8
        for (int u = 0; u < HH; u++) {
            float wv = Wd[u*HH + w];
            ull w2 = pack2(wv, wv);
            a2[0] = fma2(*(const ull*)&sT[u][2*h2], w2, a2[0]);
            a2[1] = fma2(*(const ull*)&sT[u][2*h2+2], w2, a2[1]);
        }
        #pragma unroll
        for (int j = 0; j < 2; j++)
            *(ull*)&g_hdp2[l][pbase + j][w][0] = mul2(a2[j], gwc[j]);
    }
}

// ---------------- KB: down accumulation + fused last-block chunk reduce ----------------
__global__ void __launch_bounds__(128) k_down() {
    __shared__ float Ssm[GM][PTILE][20];
    int t  = threadIdx.x;
    int m0 = blockIdx.x * GM;
    int p0 = blockIdx.y * PTILE;

    double sd = MIN_STDD + (MAX_STDD-MIN_STDD)*(double)t/127.0;
    float niv = (float)(-1.4426950408889634/(2.0*sd*sd));
    ull niv2 = pack2(niv, niv);

    for (int i = t; i < GM*PTILE*5; i += 128) {
        int mi = i/(PTILE*5); int rem = i%(PTILE*5); int p = rem/5; int j = rem%5;
        *(float4*)&Ssm[mi][p][4*j] = *(const float4*)&g_S2[m0+mi][p0+p][4*j];
    }
    ull acc[GM][9];
    #pragma unroll
    for (int mi = 0; mi < GM; mi++)
        #pragma unroll
        for (int k = 0; k < 9; k++) acc[mi][k] = 0ull;
    __syncthreads();

    ull h0 = *(const ull*)&g_hdp2[0][p0][t][0];
    ull h1 = *(const ull*)&g_hdp2[1][p0][t][0];
    ull h2 = *(const ull*)&g_hdp2[2][p0][t][0];

    #pragma unroll 1
    for (int p = 0; p < PTILE; p++) {
        ull c0 = h0, c1 = h1, c2 = h2;
        if (p + 1 < PTILE) {
            h0 = *(const ull*)&g_hdp2[0][p0+p+1][t][0];
            h1 = *(const ull*)&g_hdp2[1][p0+p+1][t][0];
            h2 = *(const ull*)&g_hdp2[2][p0+p+1][t][0];
        }
        #pragma unroll
        for (int mi = 0; mi < GM; mi++) {
            const float* sp = &Ssm[mi][p][0];
            ulonglong2 q01 = *(const ulonglong2*)(sp);
            ulonglong2 q23 = *(const ulonglong2*)(sp + 4);
            ulonglong2 q45 = *(const ulonglong2*)(sp + 8);
            ulonglong2 q67 = *(const ulonglong2*)(sp + 12);
            ull x2p = *(const ull*)(sp + 16);
            ull qq  = mul2(x2p, niv2);
            float2 ef = unpk2(qq);
            ull ep  = pack2(ex2f(ef.x), ex2f(ef.y));
            ull rp  = mul2(ep, x2p);
            ull t0 = mul2(c0, rp), t1 = mul2(c1, rp), t2 = mul2(c2, rp);
            acc[mi][0] = add2(acc[mi][0], t0);
            acc[mi][1] = fma2(t1, q01.x, acc[mi][1]);
            acc[mi][2] = fma2(t1, q01.y, acc[mi][2]);
            acc[mi][3] = fma2(t1, q23.x, acc[mi][3]);
            acc[mi][4] = fma2(t2, q23.y, acc[mi][4]);
            acc[mi][5] = fma2(t2, q45.x, acc[mi][5]);
            acc[mi][6] = fma2(t2, q45.y, acc[mi][6]);
            acc[mi][7] = fma2(t2, q67.x, acc[mi][7]);
            acc[mi][8] = fma2(t2, q67.y, acc[mi][8]);
        }
    }
    #pragma unroll
    for (int mi = 0; mi < GM; mi++)
        #pragma unroll
        for (int k = 0; k < 9; k++) {
            float2 f = unpk2(acc[mi][k]);
            g_coarse[blockIdx.y][m0+mi][k][t] = f.x + f.y;
        }

    __threadfence();
    __shared__ int lastflag;
    if (t == 0) {
        unsigned old = atomicAdd(&g_cnt[blockIdx.x], 1u);
        lastflag = (old == NCHUNK - 1);
    }
    __syncthreads();
    if (!lastflag) return;
    __threadfence();

    #pragma unroll 1
    for (int mi = 0; mi < GM; mi++) {
        #pragma unroll
        for (int k = 0; k < 9; k++) {
            float s = 0.f;
            #pragma unroll
            for (int ch = 0; ch < NCHUNK; ch++)
                s += g_coarse[ch][m0+mi][k][t];
            g_cr[m0+mi][k][t] = s;
        }
    }
    if (t == 0) g_cnt[blockIdx.x] = 0;
}

// ---------------- KC: CU = coarse @ Wup, one block per (m, l) ----------------
__global__ void __launch_bounds__(128) k_gemm(const float* __restrict__ Wup) {
    __shared__ float csm[5][HH];
    int m = blockIdx.x;
    int l = blockIdx.y;
    int t = threadIdx.x;
    const float* Wl = Wup + l*HH*HH;

    if (l == 0) {
        csm[0][t] = g_cr[m][0][t];
        __syncthreads();
        float a = 0.f;
        #pragma unroll 8
        for (int u = 0; u < HH; u++) a += csm[0][u] * Wl[u*HH + t];
        g_CU[m][0][t] = a;
    } else if (l == 1) {
        #pragma unroll
        for (int k = 0; k < 3; k++) csm[k][t] = g_cr[m][1+k][t];
        __syncthreads();
        float a0 = 0.f, a1 = 0.f, a2 = 0.f;
        #pragma unroll 8
        for (int u = 0; u < HH; u++) {
            float wv = Wl[u*HH + t];
            a0 += csm[0][u]*wv; a1 += csm[1][u]*wv; a2 += csm[2][u]*wv;
        }
        g_CU[m][1][t] = a0; g_CU[m][2][t] = a1; g_CU[m][3][t] = a2;
    } else {
        #pragma unroll
        for (int k = 0; k < 5; k++) csm[k][t] = g_cr[m][4+k][t];
        __syncthreads();
        float a0=0.f,a1=0.f,a2=0.f,a3=0.f,a4=0.f;
        #pragma unroll 8
        for (int u = 0; u < HH; u++) {
            float wv = Wl[u*HH + t];
            a0 += csm[0][u]*wv; a1 += csm[1][u]*wv; a2 += csm[2][u]*wv;
            a3 += csm[3][u]*wv; a4 += csm[4][u]*wv;
        }
        g_CU[m][4][t]=a0; g_CU[m][5][t]=a1; g_CU[m][6][t]=a2;
        g_CU[m][7][t]=a3; g_CU[m][8][t]=a4;
    }
}

// ---------------- KD: split-K up contraction, CU in registers, 1 sync/stage ----------------
// grid (64 n-tiles, 8 m-splits), 256 threads. Tile: 16 pairs x 16 m-stages.
__global__ void __launch_bounds__(256) k_upA() {
    __shared__ float Ss[2][16*20];     // 1.28 KB x2
    int t = threadIdx.x;
    int w = t & 127, q = t >> 7;       // q in {0,1}: pairs q*8..q*8+7
    int p0 = blockIdx.x * 16;
    int mbase = blockIdx.y * MPS;

    bool doS = (t < 80);               // 80 float4 per S stage
    float4 rS;
    if (doS) rS = ((const float4*)&g_S2[mbase][p0][0])[t];

    float cu[9], cuN[9];
    #pragma unroll
    for (int k = 0; k < 9; k++) cu[k] = g_CU[mbase][k][w];

    if (doS) ((float4*)&Ss[0][0])[t] = rS;
    __syncthreads();

    ull acc[8];
    #pragma unroll
    for (int j = 0; j < 8; j++) acc[j] = 0ull;

    #pragma unroll 1
    for (int s = 0; s < MPS; s++) {
        int buf = s & 1;
        if (s + 1 < MPS) {
            int m1 = mbase + s + 1;
            if (doS) rS = ((const float4*)&g_S2[m1][p0][0])[t];
            #pragma unroll
            for (int k = 0; k < 9; k++) cuN[k] = g_CU[m1][k][w];
        }
        ull cup[9];
        #pragma unroll
        for (int k = 0; k < 9; k++) cup[k] = pack2(cu[k], cu[k]);
        #pragma unroll
        for (int j = 0; j < 8; j++) {
            const float* sp = &Ss[buf][(q*8 + j)*20];
            ulonglong2 q01 = *(const ulonglong2*)(sp);
            ulonglong2 q23 = *(const ulonglong2*)(sp + 4);
            ulonglong2 q45 = *(const ulonglong2*)(sp + 8);
            ulonglong2 q67 = *(const ulonglong2*)(sp + 12);
            ull a = acc[j];
            a = add2(a, cup[0]);
            a = fma2(cup[1], q01.x, a);
            a = fma2(cup[2], q01.y, a);
            a = fma2(cup[3], q23.x, a);
            a = fma2(cup[4], q23.y, a);
            a = fma2(cup[5], q45.x, a);
            a = fma2(cup[6], q45.y, a);
            a = fma2(cup[7], q67.x, a);
            a = fma2(cup[8], q67.y, a);
            acc[j] = a;
        }
        if (s + 1 < MPS) {
            #pragma unroll
            for (int k = 0; k < 9; k++) cu[k] = cuN[k];
            if (doS) ((float4*)&Ss[buf ^ 1][0])[t] = rS;
        }
        __syncthreads();
    }

    #pragma unroll
    for (int j = 0; j < 8; j++)
        g_part[blockIdx.y][p0 + q*8 + j][w] = acc[j];
}

// ---------------- KE: sum partials + post-MLP + silu -> out ----------------
__global__ void __launch_bounds__(256) k_fin(const float* __restrict__ Wpost,
                                             const float* __restrict__ bpost,
                                             float* __restrict__ out) {
    __shared__ ull osm[4][HH];
    int t = threadIdx.x;
    int w = t & 127, q = t >> 7;
    int p0 = blockIdx.x * 4;

    #pragma unroll
    for (int j = 0; j < 2; j++) {
        int p = p0 + q*2 + j;
        ull s = 0ull;
        #pragma unroll
        for (int sp = 0; sp < MSPLIT; sp++)
            s = add2(s, g_part[sp][p][w]);
        osm[q*2 + j][w] = s;
    }
    __syncthreads();

    float bp = bpost[w];
    ull fo0 = pack2(bp, bp), fo1 = pack2(bp, bp);
    #pragma unroll 8
    for (int u = 0; u < HH; u++) {
        float wv = Wpost[u*HH + w];
        ull wv2 = pack2(wv, wv);
        fo0 = fma2(osm[q*2 + 0][u], wv2, fo0);
        fo1 = fma2(osm[q*2 + 1][u], wv2, fo1);
    }
    float2 f0 = unpk2(fo0), f1 = unpk2(fo1);
    int r0i = 2*(p0 + 2*q);
    out[(long)(r0i+0)*HH + w] = f0.x/(1.f+__expf(-f0.x));
    out[(long)(r0i+1)*HH + w] = f0.y/(1.f+__expf(-f0.y));
    out[(long)(r0i+2)*HH + w] = f1.x/(1.f+__expf(-f1.x));
    out[(long)(r0i+3)*HH + w] = f1.y/(1.f+__expf(-f1.y));
}

// ---------------- launch ----------------
extern "C" void kernel_launch(void* const* d_in, const int* in_sizes, int n_in,
                              void* d_out, int out_size) {
    const float* h     = (const float*)d_in[0];
    const float* gc    = (const float*)d_in[1];
    const float* cc    = (const float*)d_in[2];
    const float* gw    = (const float*)d_in[3];
    const float* Wpre  = (const float*)d_in[4];
    const float* bpre  = (const float*)d_in[5];
    const float* Wdown = (const float*)d_in[6];
    const float* Wup   = (const float*)d_in[7];
    const float* Wpost = (const float*)d_in[8];
    const float* bpost = (const float*)d_in[9];
    float* out = (float*)d_out;

    kA    <<<384, 256>>>(gc, cc, h, Wpre, bpre, Wdown, gw);
    k_down<<<dim3(MM/GM, NCHUNK), 128>>>();
    k_gemm<<<dim3(MM, 3), 128>>>(Wup);
    k_upA <<<dim3(NP/16, MSPLIT), 256>>>();
    k_fin <<<NP/4, 256>>>(Wpost, bpost, out);
}